// round 5
// baseline (speedup 1.0000x reference)
#include <cuda_runtime.h>
#include <cstdint>

#define B_MAX   8
#define P_MAX   140000
#define NBINS   4096
#define CAP     8192       // compact buffer per batch (power of two, bitonic size)
#define NMS_K   5000       // candidates considered by NMS
#define NWORDS  157        // ceil(5000/32)
#define PAD     5120       // padded row length (i-dim) of transposed matrix
#define TOPK    750        // rows emitted per class
#define CONF_TH 0.05f
#define NMS_TH  0.3f
#define FULL    0xffffffffu

// ---------------- scratch (static device globals; no allocation) ----------------
__device__ float              g_scores[B_MAX * P_MAX];
__device__ unsigned int       g_hist  [B_MAX * NBINS];
__device__ int                g_cnt   [B_MAX];
__device__ int                g_cutbin[B_MAX];
__device__ unsigned long long g_keys  [B_MAX * CAP];
__device__ float              g_cscore[B_MAX * NMS_K];
__device__ float4             g_cbox  [B_MAX * NMS_K];
__device__ float              g_carea [B_MAX * NMS_K];
// transposed suppression matrix: g_matT[(b*NWORDS + w)*PAD + i] = 32 bits (j = w*32+lane)
__device__ unsigned int       g_matT  [(size_t)B_MAX * NWORDS * PAD];

// ---------------- init: zero output + scratch ----------------
__global__ void init_kernel(float* __restrict__ out, int out_size, int B) {
    int stride = gridDim.x * blockDim.x;
    int t = blockIdx.x * blockDim.x + threadIdx.x;
    for (int i = t; i < out_size; i += stride) out[i] = 0.0f;
    for (int i = t; i < B * NBINS; i += stride) g_hist[i] = 0u;
    for (int i = t; i < B; i += stride) g_cnt[i] = 0;
    for (int i = t; i < B * CAP; i += stride) g_keys[i] = ~0ull;
}

// ---------------- scores: softmax class-1 prob, threshold, histogram ----------------
__global__ void score_kernel(const float* __restrict__ conf, int P) {
    int b = blockIdx.y;
    int idx = (blockIdx.x * blockDim.x + threadIdx.x) * 2;
    if (idx >= P) return;
    size_t off = (size_t)b * P + idx;                    // even
    float4 c = reinterpret_cast<const float4*>(conf)[off >> 1];
    #pragma unroll
    for (int q = 0; q < 2; q++) {
        if (idx + q >= P) break;
        float c0 = q ? c.z : c.x;
        float c1 = q ? c.w : c.y;
        float m  = fmaxf(c0, c1);
        float e0 = expf(c0 - m);
        float e1 = expf(c1 - m);
        float s  = __fdiv_rn(e1, e0 + e1);               // == softmax(...)[...,1]
        float th = (s > CONF_TH) ? s : -1.0f;
        g_scores[off + q] = th;
        if (th > 0.0f) {
            int bin = (int)(th * (float)NBINS);
            bin = (bin > NBINS - 1) ? NBINS - 1 : (bin < 0 ? 0 : bin);
            atomicAdd(&g_hist[b * NBINS + bin], 1u);
        }
    }
}

// ---------------- cutoff: smallest bin t s.t. suffix count >= NMS_K ----------------
__global__ void cutoff_kernel() {
    int b = blockIdx.x;
    __shared__ unsigned int csum[256];
    int tid = threadIdx.x;
    unsigned int sum = 0;
    #pragma unroll
    for (int i = 0; i < NBINS / 256; i++) sum += g_hist[b * NBINS + tid * (NBINS / 256) + i];
    csum[tid] = sum;
    __syncthreads();
    if (tid == 0) {
        unsigned int acc = 0;
        int c = 255;
        for (; c >= 0; c--) {
            if (acc + csum[c] >= (unsigned)NMS_K) break;
            acc += csum[c];
        }
        int cut = 0;
        if (c >= 0) {
            int bin = c * (NBINS / 256) + (NBINS / 256) - 1;
            for (; bin >= c * (NBINS / 256); bin--) {
                acc += g_hist[b * NBINS + bin];
                if (acc >= (unsigned)NMS_K) break;
            }
            cut = (bin < c * (NBINS / 256)) ? c * (NBINS / 256) : bin;
        }
        g_cutbin[b] = cut;
    }
}

// ---------------- compact: warp-aggregated gather of candidates above cutoff ----------------
__global__ void compact_kernel(int P) {
    int b = blockIdx.y;
    int lane = threadIdx.x & 31;
    int base = (blockIdx.x * blockDim.x + threadIdx.x) * 4;
    int cut  = g_cutbin[b];
    unsigned long long keys[4];
    int c = 0;
    if (base < P) {
        float4 s4 = *reinterpret_cast<const float4*>(&g_scores[(size_t)b * P + base]);
        float sv[4] = {s4.x, s4.y, s4.z, s4.w};
        #pragma unroll
        for (int q = 0; q < 4; q++) {
            if (base + q < P) {
                float th = sv[q];
                if (th > 0.0f) {
                    int bin = (int)(th * (float)NBINS);
                    bin = (bin > NBINS - 1) ? NBINS - 1 : (bin < 0 ? 0 : bin);
                    if (bin >= cut) {
                        unsigned kb = __float_as_uint(th);
                        keys[c++] = ((unsigned long long)(~kb) << 32) | (unsigned)(base + q);
                    }
                }
            }
        }
    }
    unsigned cnt = (unsigned)c;
    #pragma unroll
    for (int d = 1; d < 32; d <<= 1) {
        unsigned n = __shfl_up_sync(FULL, cnt, d);
        if (lane >= d) cnt += n;
    }
    unsigned tot = __shfl_sync(FULL, cnt, 31);
    int basepos = 0;
    if (lane == 31 && tot) basepos = atomicAdd(&g_cnt[b], (int)tot);
    basepos = __shfl_sync(FULL, basepos, 31);
    int pos = basepos + (int)(cnt - (unsigned)c);
    for (int q = 0; q < c; q++, pos++)
        if (pos < CAP) g_keys[(size_t)b * CAP + pos] = keys[q];
}

// ---------------- per-batch bitonic sort of CAP keys + decode top NMS_K boxes ----------------
__global__ void sort_kernel(const float* __restrict__ loc, const float* __restrict__ prior,
                            int P) {
    extern __shared__ unsigned long long sm[];
    int b = blockIdx.x, tid = threadIdx.x, T = blockDim.x;
    for (int i = tid; i < CAP; i += T) sm[i] = g_keys[(size_t)b * CAP + i];
    __syncthreads();
    for (int k = 2; k <= CAP; k <<= 1) {
        for (int j = k >> 1; j > 0; j >>= 1) {
            for (int i = tid; i < CAP; i += T) {
                int ixj = i ^ j;
                if (ixj > i) {
                    unsigned long long a = sm[i], c = sm[ixj];
                    bool up = ((i & k) == 0);
                    if ((a > c) == up) { sm[i] = c; sm[ixj] = a; }
                }
            }
            __syncthreads();
        }
    }
    for (int i = tid; i < NMS_K; i += T) {
        unsigned long long key = sm[i];
        unsigned int idx = (unsigned int)key;
        int o = b * NMS_K + i;
        if (idx < (unsigned int)P) {
            float  sc = g_scores[(size_t)b * P + idx];
            float4 l  = reinterpret_cast<const float4*>(loc)[(size_t)b * P + idx];
            float4 pr = reinterpret_cast<const float4*>(prior)[idx];
            float cx = pr.x + l.x * 0.1f * pr.z;
            float cy = pr.y + l.y * 0.1f * pr.w;
            float w  = pr.z * expf(l.z * 0.2f);
            float h  = pr.w * expf(l.w * 0.2f);
            float x1 = cx - w * 0.5f;
            float y1 = cy - h * 0.5f;
            float x2 = x1 + w;
            float y2 = y1 + h;
            g_cscore[o] = sc;
            g_cbox[o]   = make_float4(x1, y1, x2, y2);
            g_carea[o]  = (x2 - x1) * (y2 - y1);
        } else {
            g_cscore[o] = -1.0f;
            g_cbox[o]   = make_float4(0.f, 0.f, 0.f, 0.f);
            g_carea[o]  = 0.0f;
        }
    }
}

// ---------------- suppression bitmatrix (transposed): g_matT[w][i] bit j' = iou(i, w*32+j')>0.3, j>i ----------------
#define ITILE 128
__global__ __launch_bounds__(256) void matrix_kernel() {
    __shared__ float4 sbi[ITILE];
    __shared__ float  sai[ITILE];
    int b  = blockIdx.y;
    int i0 = blockIdx.x * ITILE;
    int tid = threadIdx.x, lane = tid & 31, wid = tid >> 5;   // 8 warps

    // preload i-tile boxes into smem
    for (int q = tid; q < ITILE; q += 256) {
        int i = i0 + q;
        if (i < NMS_K) { sbi[q] = g_cbox[b * NMS_K + i]; sai[q] = g_carea[b * NMS_K + i]; }
        else           { sbi[q] = make_float4(0,0,0,0);  sai[q] = 0.f; }
    }
    __syncthreads();

    int ilim = min(ITILE, NMS_K - i0);
    int w0   = i0 >> 5;
    for (int w = w0 + wid; w < NWORDS; w += 8) {
        int j = w * 32 + lane;
        bool jv = j < NMS_K;
        float4 bj = jv ? g_cbox[b * NMS_K + j] : make_float4(0,0,0,0);
        float  aj = jv ? g_carea[b * NMS_K + j] : 0.f;
        size_t base = ((size_t)(b * NWORDS + w)) * PAD + i0;
        unsigned myw = 0;
        for (int ii = 0; ii < ilim; ii++) {
            int i = i0 + ii;
            float4 bi = sbi[ii];                      // broadcast (conflict-free)
            float  ai = sai[ii];
            float xx1 = fmaxf(bj.x, bi.x), yy1 = fmaxf(bj.y, bi.y);
            float xx2 = fminf(bj.z, bi.z), yy2 = fminf(bj.w, bi.w);
            float inter = fmaxf(xx2 - xx1, 0.f) * fmaxf(yy2 - yy1, 0.f);
            float uni   = aj - inter + ai;
            bool flag = jv && (j > i) && (__fdiv_rn(inter, uni) > NMS_TH);  // exact ref semantics
            unsigned bal = __ballot_sync(FULL, flag);
            if ((ii & 31) == lane) myw = bal;         // each lane keeps its slot's word
            if ((ii & 31) == 31) g_matT[base + (ii - 31) + lane] = myw;   // coalesced
        }
        if (ilim & 31) g_matT[base + (ilim & ~31) + lane] = myw;          // partial-tile flush
    }
}

// ---------------- greedy sweep: per-word latency batching ----------------
__global__ void sweep_kernel(float* __restrict__ out) {
    __shared__ unsigned validw[NWORDS];
    __shared__ int      s_acc[TOPK];
    __shared__ int      s_cnt;

    int b = blockIdx.x, tid = threadIdx.x, lane = tid & 31, wid = tid >> 5;

    // valid bitmask per word (score > 0)
    for (int w = wid; w < NWORDS; w += 8) {
        int i = w * 32 + lane;
        unsigned m = __ballot_sync(FULL, (i < NMS_K) && (g_cscore[b * NMS_K + i] > 0.0f));
        if (lane == 0) validw[w] = m;
    }
    __syncthreads();

    if (wid == 0) {
        int cnt = 0;
        for (int w = 0; w < NWORDS && cnt < TOPK; w++) {
            size_t base = ((size_t)(b * NWORDS + w)) * PAD;
            // suppression from previously accepted (parallel loads, one latency)
            unsigned rem = 0;
            for (int q = lane; q < cnt; q += 32)
                rem |= g_matT[base + s_acc[q]];
            rem = __reduce_or_sync(FULL, rem);
            // diagonal word: intra-word suppression rows (coalesced)
            unsigned pre = g_matT[base + w * 32 + lane];
            unsigned avail = validw[w] & ~rem;
            while (avail && cnt < TOPK) {
                int bit = __ffs(avail) - 1;
                int i = w * 32 + bit;
                if (lane == 0) s_acc[cnt] = i;
                cnt++;
                avail &= ~(1u << bit);
                avail &= ~__shfl_sync(FULL, pre, bit);
            }
            __syncwarp();
        }
        if (lane == 0) s_cnt = cnt;
    }
    __syncthreads();

    // parallel output emit (accepted order == emit order)
    int cnt = s_cnt;
    float* orow = out + ((size_t)b * 2 + 1) * TOPK * 5;   // class 1
    for (int t = tid; t < cnt; t += blockDim.x) {
        int i = s_acc[t];
        float4 bb = g_cbox[b * NMS_K + i];
        float  sc = g_cscore[b * NMS_K + i];
        float* r = orow + t * 5;
        r[0] = sc; r[1] = bb.x; r[2] = bb.y; r[3] = bb.z; r[4] = bb.w;
    }
}

// ---------------- launch ----------------
extern "C" void kernel_launch(void* const* d_in, const int* in_sizes, int n_in,
                              void* d_out, int out_size) {
    const float* loc   = (const float*)d_in[0];   // [B,P,4]
    const float* conf  = (const float*)d_in[1];   // [B,P,2]
    const float* prior = (const float*)d_in[2];   // [P,4]

    int P = in_sizes[2] / 4;
    int B = in_sizes[1] / (2 * P);
    if (B > B_MAX) B = B_MAX;
    if (P > P_MAX) P = P_MAX;

    float* out = (float*)d_out;

    static const size_t SORT_SMEM = (size_t)CAP * sizeof(unsigned long long);   // 64 KB
    cudaFuncSetAttribute(sort_kernel, cudaFuncAttributeMaxDynamicSharedMemorySize, (int)SORT_SMEM);

    init_kernel<<<256, 256>>>(out, out_size, B);

    dim3 gscore((P + 511) / 512, B);
    score_kernel<<<gscore, 256>>>(conf, P);

    cutoff_kernel<<<B, 256>>>();

    dim3 gcomp((P + 1023) / 1024, B);
    compact_kernel<<<gcomp, 256>>>(P);

    sort_kernel<<<B, 1024, SORT_SMEM>>>(loc, prior, P);

    dim3 gmat((NMS_K + ITILE - 1) / ITILE, B);
    matrix_kernel<<<gmat, 256>>>();

    sweep_kernel<<<B, 256>>>(out);
}

// round 6
// speedup vs baseline: 1.0052x; 1.0052x over previous
#include <cuda_runtime.h>
#include <cstdint>

#define B_MAX   8
#define P_MAX   140000
#define NBINS   4096
#define CAP     8192       // compact buffer per batch (power of two, bitonic size)
#define NMS_K   5000       // candidates considered by NMS
#define NWORDS  157        // ceil(5000/32)
#define PAD     5120       // padded row length (i-dim) of transposed matrix
#define TOPK    750        // rows emitted per class
#define CONF_TH 0.05f
#define NMS_TH  0.3f
#define FULL    0xffffffffu

// ---------------- scratch (static device globals; no allocation) ----------------
__device__ float              g_scores[B_MAX * P_MAX];
__device__ unsigned int       g_hist  [B_MAX * NBINS];
__device__ int                g_cnt   [B_MAX];
__device__ int                g_cutbin[B_MAX];
__device__ unsigned long long g_keys  [B_MAX * CAP];
__device__ float              g_cscore[B_MAX * NMS_K];
__device__ float4             g_cbox  [B_MAX * NMS_K];
__device__ float              g_carea [B_MAX * NMS_K];
// transposed suppression matrix: g_matT[(b*NWORDS + w)*PAD + i] = 32 bits (j = w*32+lane)
__device__ unsigned int       g_matT  [(size_t)B_MAX * NWORDS * PAD];

// ---------------- init: zero output + scratch ----------------
__global__ void init_kernel(float* __restrict__ out, int out_size, int B) {
    int stride = gridDim.x * blockDim.x;
    int t = blockIdx.x * blockDim.x + threadIdx.x;
    for (int i = t; i < out_size; i += stride) out[i] = 0.0f;
    for (int i = t; i < B * NBINS; i += stride) g_hist[i] = 0u;
    for (int i = t; i < B; i += stride) g_cnt[i] = 0;
    for (int i = t; i < B * CAP; i += stride) g_keys[i] = ~0ull;
}

// ---------------- scores: softmax class-1 prob, threshold, histogram ----------------
__global__ void score_kernel(const float* __restrict__ conf, int P) {
    int b = blockIdx.y;
    int idx = (blockIdx.x * blockDim.x + threadIdx.x) * 2;
    if (idx >= P) return;
    size_t off = (size_t)b * P + idx;                    // even
    float4 c = reinterpret_cast<const float4*>(conf)[off >> 1];
    #pragma unroll
    for (int q = 0; q < 2; q++) {
        if (idx + q >= P) break;
        float c0 = q ? c.z : c.x;
        float c1 = q ? c.w : c.y;
        float m  = fmaxf(c0, c1);
        float e0 = expf(c0 - m);
        float e1 = expf(c1 - m);
        float s  = __fdiv_rn(e1, e0 + e1);               // == softmax(...)[...,1]
        float th = (s > CONF_TH) ? s : -1.0f;
        g_scores[off + q] = th;
        if (th > 0.0f) {
            int bin = (int)(th * (float)NBINS);
            bin = (bin > NBINS - 1) ? NBINS - 1 : (bin < 0 ? 0 : bin);
            atomicAdd(&g_hist[b * NBINS + bin], 1u);
        }
    }
}

// ---------------- cutoff: smallest bin t s.t. suffix count >= NMS_K ----------------
__global__ void cutoff_kernel() {
    int b = blockIdx.x;
    __shared__ unsigned int csum[256];
    int tid = threadIdx.x;
    unsigned int sum = 0;
    #pragma unroll
    for (int i = 0; i < NBINS / 256; i++) sum += g_hist[b * NBINS + tid * (NBINS / 256) + i];
    csum[tid] = sum;
    __syncthreads();
    if (tid == 0) {
        unsigned int acc = 0;
        int c = 255;
        for (; c >= 0; c--) {
            if (acc + csum[c] >= (unsigned)NMS_K) break;
            acc += csum[c];
        }
        int cut = 0;
        if (c >= 0) {
            int bin = c * (NBINS / 256) + (NBINS / 256) - 1;
            for (; bin >= c * (NBINS / 256); bin--) {
                acc += g_hist[b * NBINS + bin];
                if (acc >= (unsigned)NMS_K) break;
            }
            cut = (bin < c * (NBINS / 256)) ? c * (NBINS / 256) : bin;
        }
        g_cutbin[b] = cut;
    }
}

// ---------------- compact: warp-aggregated gather of candidates above cutoff ----------------
__global__ void compact_kernel(int P) {
    int b = blockIdx.y;
    int lane = threadIdx.x & 31;
    int base = (blockIdx.x * blockDim.x + threadIdx.x) * 4;
    int cut  = g_cutbin[b];
    unsigned long long keys[4];
    int c = 0;
    if (base < P) {
        float4 s4 = *reinterpret_cast<const float4*>(&g_scores[(size_t)b * P + base]);
        float sv[4] = {s4.x, s4.y, s4.z, s4.w};
        #pragma unroll
        for (int q = 0; q < 4; q++) {
            if (base + q < P) {
                float th = sv[q];
                if (th > 0.0f) {
                    int bin = (int)(th * (float)NBINS);
                    bin = (bin > NBINS - 1) ? NBINS - 1 : (bin < 0 ? 0 : bin);
                    if (bin >= cut) {
                        unsigned kb = __float_as_uint(th);
                        keys[c++] = ((unsigned long long)(~kb) << 32) | (unsigned)(base + q);
                    }
                }
            }
        }
    }
    unsigned cnt = (unsigned)c;
    #pragma unroll
    for (int d = 1; d < 32; d <<= 1) {
        unsigned n = __shfl_up_sync(FULL, cnt, d);
        if (lane >= d) cnt += n;
    }
    unsigned tot = __shfl_sync(FULL, cnt, 31);
    int basepos = 0;
    if (lane == 31 && tot) basepos = atomicAdd(&g_cnt[b], (int)tot);
    basepos = __shfl_sync(FULL, basepos, 31);
    int pos = basepos + (int)(cnt - (unsigned)c);
    for (int q = 0; q < c; q++, pos++)
        if (pos < CAP) g_keys[(size_t)b * CAP + pos] = keys[q];
}

// ---------------- per-batch bitonic sort of CAP keys + decode top NMS_K boxes ----------------
__global__ void sort_kernel(const float* __restrict__ loc, const float* __restrict__ prior,
                            int P) {
    extern __shared__ unsigned long long sm[];
    int b = blockIdx.x, tid = threadIdx.x, T = blockDim.x;
    for (int i = tid; i < CAP; i += T) sm[i] = g_keys[(size_t)b * CAP + i];
    __syncthreads();
    for (int k = 2; k <= CAP; k <<= 1) {
        for (int j = k >> 1; j > 0; j >>= 1) {
            for (int i = tid; i < CAP; i += T) {
                int ixj = i ^ j;
                if (ixj > i) {
                    unsigned long long a = sm[i], c = sm[ixj];
                    bool up = ((i & k) == 0);
                    if ((a > c) == up) { sm[i] = c; sm[ixj] = a; }
                }
            }
            __syncthreads();
        }
    }
    for (int i = tid; i < NMS_K; i += T) {
        unsigned long long key = sm[i];
        unsigned int idx = (unsigned int)key;
        int o = b * NMS_K + i;
        if (idx < (unsigned int)P) {
            float  sc = g_scores[(size_t)b * P + idx];
            float4 l  = reinterpret_cast<const float4*>(loc)[(size_t)b * P + idx];
            float4 pr = reinterpret_cast<const float4*>(prior)[idx];
            float cx = pr.x + l.x * 0.1f * pr.z;
            float cy = pr.y + l.y * 0.1f * pr.w;
            float w  = pr.z * expf(l.z * 0.2f);
            float h  = pr.w * expf(l.w * 0.2f);
            float x1 = cx - w * 0.5f;
            float y1 = cy - h * 0.5f;
            float x2 = x1 + w;
            float y2 = y1 + h;
            g_cscore[o] = sc;
            g_cbox[o]   = make_float4(x1, y1, x2, y2);
            g_carea[o]  = (x2 - x1) * (y2 - y1);
        } else {
            g_cscore[o] = -1.0f;
            g_cbox[o]   = make_float4(0.f, 0.f, 0.f, 0.f);
            g_carea[o]  = 0.0f;
        }
    }
}

// ---------------- suppression bitmatrix (transposed): g_matT[w][i] bit j' = iou(i, w*32+j')>0.3, j>i ----------------
#define ITILE 128
__global__ __launch_bounds__(256) void matrix_kernel() {
    __shared__ float4 sbi[ITILE];
    __shared__ float  sai[ITILE];
    int b  = blockIdx.y;
    int i0 = blockIdx.x * ITILE;
    int tid = threadIdx.x, lane = tid & 31, wid = tid >> 5;   // 8 warps

    // preload i-tile boxes into smem
    for (int q = tid; q < ITILE; q += 256) {
        int i = i0 + q;
        if (i < NMS_K) { sbi[q] = g_cbox[b * NMS_K + i]; sai[q] = g_carea[b * NMS_K + i]; }
        else           { sbi[q] = make_float4(0,0,0,0);  sai[q] = 0.f; }
    }
    __syncthreads();

    int ilim = min(ITILE, NMS_K - i0);
    int w0   = i0 >> 5;
    for (int w = w0 + wid; w < NWORDS; w += 8) {
        int j = w * 32 + lane;
        bool jv = j < NMS_K;
        float4 bj = jv ? g_cbox[b * NMS_K + j] : make_float4(0,0,0,0);
        float  aj = jv ? g_carea[b * NMS_K + j] : 0.f;
        size_t base = ((size_t)(b * NWORDS + w)) * PAD + i0;
        unsigned myw = 0;
        for (int ii = 0; ii < ilim; ii++) {
            int i = i0 + ii;
            float4 bi = sbi[ii];                      // broadcast (conflict-free)
            float  ai = sai[ii];
            float xx1 = fmaxf(bj.x, bi.x), yy1 = fmaxf(bj.y, bi.y);
            float xx2 = fminf(bj.z, bi.z), yy2 = fminf(bj.w, bi.w);
            float inter = fmaxf(xx2 - xx1, 0.f) * fmaxf(yy2 - yy1, 0.f);
            float uni   = aj - inter + ai;
            bool flag = jv && (j > i) && (__fdiv_rn(inter, uni) > NMS_TH);  // exact ref semantics
            unsigned bal = __ballot_sync(FULL, flag);
            if ((ii & 31) == lane) myw = bal;         // each lane keeps its slot's word
            if ((ii & 31) == 31) g_matT[base + (ii - 31) + lane] = myw;   // coalesced
        }
        if (ilim & 31) g_matT[base + (ilim & ~31) + lane] = myw;          // partial-tile flush
    }
}

// ---------------- greedy sweep: per-word latency batching ----------------
__global__ void sweep_kernel(float* __restrict__ out) {
    __shared__ unsigned validw[NWORDS];
    __shared__ int      s_acc[TOPK];
    __shared__ int      s_cnt;

    int b = blockIdx.x, tid = threadIdx.x, lane = tid & 31, wid = tid >> 5;

    // valid bitmask per word (score > 0)
    for (int w = wid; w < NWORDS; w += 8) {
        int i = w * 32 + lane;
        unsigned m = __ballot_sync(FULL, (i < NMS_K) && (g_cscore[b * NMS_K + i] > 0.0f));
        if (lane == 0) validw[w] = m;
    }
    __syncthreads();

    if (wid == 0) {
        int cnt = 0;
        for (int w = 0; w < NWORDS && cnt < TOPK; w++) {
            size_t base = ((size_t)(b * NWORDS + w)) * PAD;
            // suppression from previously accepted (parallel loads, one latency)
            unsigned rem = 0;
            for (int q = lane; q < cnt; q += 32)
                rem |= g_matT[base + s_acc[q]];
            rem = __reduce_or_sync(FULL, rem);
            // diagonal word: intra-word suppression rows (coalesced)
            unsigned pre = g_matT[base + w * 32 + lane];
            unsigned avail = validw[w] & ~rem;
            while (avail && cnt < TOPK) {
                int bit = __ffs(avail) - 1;
                int i = w * 32 + bit;
                if (lane == 0) s_acc[cnt] = i;
                cnt++;
                avail &= ~(1u << bit);
                avail &= ~__shfl_sync(FULL, pre, bit);
            }
            __syncwarp();
        }
        if (lane == 0) s_cnt = cnt;
    }
    __syncthreads();

    // parallel output emit (accepted order == emit order)
    int cnt = s_cnt;
    float* orow = out + ((size_t)b * 2 + 1) * TOPK * 5;   // class 1
    for (int t = tid; t < cnt; t += blockDim.x) {
        int i = s_acc[t];
        float4 bb = g_cbox[b * NMS_K + i];
        float  sc = g_cscore[b * NMS_K + i];
        float* r = orow + t * 5;
        r[0] = sc; r[1] = bb.x; r[2] = bb.y; r[3] = bb.z; r[4] = bb.w;
    }
}

// ---------------- launch ----------------
extern "C" void kernel_launch(void* const* d_in, const int* in_sizes, int n_in,
                              void* d_out, int out_size) {
    const float* loc   = (const float*)d_in[0];   // [B,P,4]
    const float* conf  = (const float*)d_in[1];   // [B,P,2]
    const float* prior = (const float*)d_in[2];   // [P,4]

    int P = in_sizes[2] / 4;
    int B = in_sizes[1] / (2 * P);
    if (B > B_MAX) B = B_MAX;
    if (P > P_MAX) P = P_MAX;

    float* out = (float*)d_out;

    static const size_t SORT_SMEM = (size_t)CAP * sizeof(unsigned long long);   // 64 KB
    cudaFuncSetAttribute(sort_kernel, cudaFuncAttributeMaxDynamicSharedMemorySize, (int)SORT_SMEM);

    init_kernel<<<256, 256>>>(out, out_size, B);

    dim3 gscore((P + 511) / 512, B);
    score_kernel<<<gscore, 256>>>(conf, P);

    cutoff_kernel<<<B, 256>>>();

    dim3 gcomp((P + 1023) / 1024, B);
    compact_kernel<<<gcomp, 256>>>(P);

    sort_kernel<<<B, 1024, SORT_SMEM>>>(loc, prior, P);

    dim3 gmat((NMS_K + ITILE - 1) / ITILE, B);
    matrix_kernel<<<gmat, 256>>>();

    sweep_kernel<<<B, 256>>>(out);
}

// round 7
// speedup vs baseline: 1.7415x; 1.7324x over previous
#include <cuda_runtime.h>
#include <cstdint>

#define B_MAX   8
#define P_MAX   140000
#define NBINS   4096
#define CAP     8192       // compact buffer per batch (power of two, bitonic size)
#define NMS_K   5000       // candidates considered by NMS
#define NWORDS  157        // ceil(5000/32)
#define PAD     5120       // padded row length (i-dim) of transposed matrix
#define TOPK    750        // rows emitted per class
#define CONF_TH 0.05f
#define NMS_TH  0.3f
#define FULL    0xffffffffu

// ---------------- scratch (static device globals; no allocation) ----------------
__device__ float              g_scores[B_MAX * P_MAX];
__device__ unsigned int       g_hist  [B_MAX * NBINS];
__device__ int                g_cnt   [B_MAX];
__device__ int                g_cutbin[B_MAX];
__device__ unsigned long long g_keys  [B_MAX * CAP];
__device__ float              g_cscore[B_MAX * NMS_K];
__device__ float4             g_cbox  [B_MAX * NMS_K];
__device__ float              g_carea [B_MAX * NMS_K];
// transposed suppression matrix: g_matT[(b*NWORDS + w)*PAD + i] = 32 bits (j = w*32+lane)
__device__ unsigned int       g_matT  [(size_t)B_MAX * NWORDS * PAD];

// ---------------- init: zero output + scratch ----------------
__global__ void init_kernel(float* __restrict__ out, int out_size, int B) {
    int stride = gridDim.x * blockDim.x;
    int t = blockIdx.x * blockDim.x + threadIdx.x;
    for (int i = t; i < out_size; i += stride) out[i] = 0.0f;
    for (int i = t; i < B * NBINS; i += stride) g_hist[i] = 0u;
    for (int i = t; i < B; i += stride) g_cnt[i] = 0;
    for (int i = t; i < B * CAP; i += stride) g_keys[i] = ~0ull;
}

// ---------------- scores: softmax class-1 prob, threshold, histogram ----------------
__global__ void score_kernel(const float* __restrict__ conf, int P) {
    int b = blockIdx.y;
    int idx = (blockIdx.x * blockDim.x + threadIdx.x) * 2;
    if (idx >= P) return;
    size_t off = (size_t)b * P + idx;                    // even
    float4 c = reinterpret_cast<const float4*>(conf)[off >> 1];
    #pragma unroll
    for (int q = 0; q < 2; q++) {
        if (idx + q >= P) break;
        float c0 = q ? c.z : c.x;
        float c1 = q ? c.w : c.y;
        float m  = fmaxf(c0, c1);
        float e0 = expf(c0 - m);
        float e1 = expf(c1 - m);
        float s  = __fdiv_rn(e1, e0 + e1);               // == softmax(...)[...,1]
        float th = (s > CONF_TH) ? s : -1.0f;
        g_scores[off + q] = th;
        if (th > 0.0f) {
            int bin = (int)(th * (float)NBINS);
            bin = (bin > NBINS - 1) ? NBINS - 1 : (bin < 0 ? 0 : bin);
            atomicAdd(&g_hist[b * NBINS + bin], 1u);
        }
    }
}

// ---------------- cutoff: smallest bin t s.t. suffix count >= NMS_K ----------------
__global__ void cutoff_kernel() {
    int b = blockIdx.x;
    __shared__ unsigned int csum[256];
    int tid = threadIdx.x;
    unsigned int sum = 0;
    #pragma unroll
    for (int i = 0; i < NBINS / 256; i++) sum += g_hist[b * NBINS + tid * (NBINS / 256) + i];
    csum[tid] = sum;
    __syncthreads();
    if (tid == 0) {
        unsigned int acc = 0;
        int c = 255;
        for (; c >= 0; c--) {
            if (acc + csum[c] >= (unsigned)NMS_K) break;
            acc += csum[c];
        }
        int cut = 0;
        if (c >= 0) {
            int bin = c * (NBINS / 256) + (NBINS / 256) - 1;
            for (; bin >= c * (NBINS / 256); bin--) {
                acc += g_hist[b * NBINS + bin];
                if (acc >= (unsigned)NMS_K) break;
            }
            cut = (bin < c * (NBINS / 256)) ? c * (NBINS / 256) : bin;
        }
        g_cutbin[b] = cut;
    }
}

// ---------------- compact: warp-aggregated gather of candidates above cutoff ----------------
__global__ void compact_kernel(int P) {
    int b = blockIdx.y;
    int lane = threadIdx.x & 31;
    int base = (blockIdx.x * blockDim.x + threadIdx.x) * 4;
    int cut  = g_cutbin[b];
    unsigned long long keys[4];
    int c = 0;
    if (base < P) {
        float4 s4 = *reinterpret_cast<const float4*>(&g_scores[(size_t)b * P + base]);
        float sv[4] = {s4.x, s4.y, s4.z, s4.w};
        #pragma unroll
        for (int q = 0; q < 4; q++) {
            if (base + q < P) {
                float th = sv[q];
                if (th > 0.0f) {
                    int bin = (int)(th * (float)NBINS);
                    bin = (bin > NBINS - 1) ? NBINS - 1 : (bin < 0 ? 0 : bin);
                    if (bin >= cut) {
                        unsigned kb = __float_as_uint(th);
                        keys[c++] = ((unsigned long long)(~kb) << 32) | (unsigned)(base + q);
                    }
                }
            }
        }
    }
    unsigned cnt = (unsigned)c;
    #pragma unroll
    for (int d = 1; d < 32; d <<= 1) {
        unsigned n = __shfl_up_sync(FULL, cnt, d);
        if (lane >= d) cnt += n;
    }
    unsigned tot = __shfl_sync(FULL, cnt, 31);
    int basepos = 0;
    if (lane == 31 && tot) basepos = atomicAdd(&g_cnt[b], (int)tot);
    basepos = __shfl_sync(FULL, basepos, 31);
    int pos = basepos + (int)(cnt - (unsigned)c);
    for (int q = 0; q < c; q++, pos++)
        if (pos < CAP) g_keys[(size_t)b * CAP + pos] = keys[q];
}

// ---------------- per-batch bitonic sort of CAP keys + decode top NMS_K boxes ----------------
__global__ void sort_kernel(const float* __restrict__ loc, const float* __restrict__ prior,
                            int P) {
    extern __shared__ unsigned long long sm[];
    int b = blockIdx.x, tid = threadIdx.x, T = blockDim.x;
    for (int i = tid; i < CAP; i += T) sm[i] = g_keys[(size_t)b * CAP + i];
    __syncthreads();
    for (int k = 2; k <= CAP; k <<= 1) {
        for (int j = k >> 1; j > 0; j >>= 1) {
            for (int i = tid; i < CAP; i += T) {
                int ixj = i ^ j;
                if (ixj > i) {
                    unsigned long long a = sm[i], c = sm[ixj];
                    bool up = ((i & k) == 0);
                    if ((a > c) == up) { sm[i] = c; sm[ixj] = a; }
                }
            }
            __syncthreads();
        }
    }
    for (int i = tid; i < NMS_K; i += T) {
        unsigned long long key = sm[i];
        unsigned int idx = (unsigned int)key;
        int o = b * NMS_K + i;
        if (idx < (unsigned int)P) {
            float  sc = g_scores[(size_t)b * P + idx];
            float4 l  = reinterpret_cast<const float4*>(loc)[(size_t)b * P + idx];
            float4 pr = reinterpret_cast<const float4*>(prior)[idx];
            float cx = pr.x + l.x * 0.1f * pr.z;
            float cy = pr.y + l.y * 0.1f * pr.w;
            float w  = pr.z * expf(l.z * 0.2f);
            float h  = pr.w * expf(l.w * 0.2f);
            float x1 = cx - w * 0.5f;
            float y1 = cy - h * 0.5f;
            float x2 = x1 + w;
            float y2 = y1 + h;
            g_cscore[o] = sc;
            g_cbox[o]   = make_float4(x1, y1, x2, y2);
            g_carea[o]  = (x2 - x1) * (y2 - y1);
        } else {
            g_cscore[o] = -1.0f;
            g_cbox[o]   = make_float4(0.f, 0.f, 0.f, 0.f);
            g_carea[o]  = 0.0f;
        }
    }
}

// ---------------- suppression bitmatrix (transposed): g_matT[w][i] bit j' = iou(i, w*32+j')>0.3, j>i ----------------
#define ITILE 128
__global__ __launch_bounds__(256) void matrix_kernel() {
    __shared__ float4 sbi[ITILE];
    __shared__ float  sai[ITILE];
    int b  = blockIdx.y;
    int i0 = blockIdx.x * ITILE;
    int tid = threadIdx.x, lane = tid & 31, wid = tid >> 5;   // 8 warps

    // preload i-tile boxes into smem
    for (int q = tid; q < ITILE; q += 256) {
        int i = i0 + q;
        if (i < NMS_K) { sbi[q] = g_cbox[b * NMS_K + i]; sai[q] = g_carea[b * NMS_K + i]; }
        else           { sbi[q] = make_float4(0,0,0,0);  sai[q] = 0.f; }
    }
    __syncthreads();

    int ilim = min(ITILE, NMS_K - i0);
    int w0   = i0 >> 5;
    for (int w = w0 + wid; w < NWORDS; w += 8) {
        int j = w * 32 + lane;
        bool jv = j < NMS_K;
        float4 bj = jv ? g_cbox[b * NMS_K + j] : make_float4(0,0,0,0);
        float  aj = jv ? g_carea[b * NMS_K + j] : 0.f;
        size_t base = ((size_t)(b * NWORDS + w)) * PAD + i0;
        unsigned myw = 0;
        for (int ii = 0; ii < ilim; ii++) {
            int i = i0 + ii;
            float4 bi = sbi[ii];                      // broadcast (conflict-free)
            float  ai = sai[ii];
            float xx1 = fmaxf(bj.x, bi.x), yy1 = fmaxf(bj.y, bi.y);
            float xx2 = fminf(bj.z, bi.z), yy2 = fminf(bj.w, bi.w);
            float inter = fmaxf(xx2 - xx1, 0.f) * fmaxf(yy2 - yy1, 0.f);
            float uni   = aj - inter + ai;
            // division-free IoU test: sign-exact vs fdiv outside a ±1e-6*|uni| band;
            // exact __fdiv_rn only in the (measure-zero) boundary band. Avoids the
            // MUFU.RCP throughput wall (rt=8/SMSP -> 74 RCP/cyc chip-wide).
            float d = fmaf(-NMS_TH, uni, inter);
            bool flag;
            if (fabsf(d) <= 1e-6f * fabsf(uni))
                flag = __fdiv_rn(inter, uni) > NMS_TH;   // rare: exact ref semantics at boundary
            else
                flag = d > 0.f;
            flag = flag && jv && (j > i);
            unsigned bal = __ballot_sync(FULL, flag);
            if ((ii & 31) == lane) myw = bal;         // each lane keeps its slot's word
            if ((ii & 31) == 31) g_matT[base + (ii - 31) + lane] = myw;   // coalesced
        }
        if (ilim & 31) g_matT[base + (ilim & ~31) + lane] = myw;          // partial-tile flush
    }
}

// ---------------- greedy sweep: per-word latency batching ----------------
__global__ void sweep_kernel(float* __restrict__ out) {
    __shared__ unsigned validw[NWORDS];
    __shared__ int      s_acc[TOPK];
    __shared__ int      s_cnt;

    int b = blockIdx.x, tid = threadIdx.x, lane = tid & 31, wid = tid >> 5;

    // valid bitmask per word (score > 0)
    for (int w = wid; w < NWORDS; w += 8) {
        int i = w * 32 + lane;
        unsigned m = __ballot_sync(FULL, (i < NMS_K) && (g_cscore[b * NMS_K + i] > 0.0f));
        if (lane == 0) validw[w] = m;
    }
    __syncthreads();

    if (wid == 0) {
        int cnt = 0;
        for (int w = 0; w < NWORDS && cnt < TOPK; w++) {
            size_t base = ((size_t)(b * NWORDS + w)) * PAD;
            // suppression from previously accepted (parallel loads, one latency)
            unsigned rem = 0;
            for (int q = lane; q < cnt; q += 32)
                rem |= g_matT[base + s_acc[q]];
            rem = __reduce_or_sync(FULL, rem);
            // diagonal word: intra-word suppression rows (coalesced)
            unsigned pre = g_matT[base + w * 32 + lane];
            unsigned avail = validw[w] & ~rem;
            while (avail && cnt < TOPK) {
                int bit = __ffs(avail) - 1;
                int i = w * 32 + bit;
                if (lane == 0) s_acc[cnt] = i;
                cnt++;
                avail &= ~(1u << bit);
                avail &= ~__shfl_sync(FULL, pre, bit);
            }
            __syncwarp();
        }
        if (lane == 0) s_cnt = cnt;
    }
    __syncthreads();

    // parallel output emit (accepted order == emit order)
    int cnt = s_cnt;
    float* orow = out + ((size_t)b * 2 + 1) * TOPK * 5;   // class 1
    for (int t = tid; t < cnt; t += blockDim.x) {
        int i = s_acc[t];
        float4 bb = g_cbox[b * NMS_K + i];
        float  sc = g_cscore[b * NMS_K + i];
        float* r = orow + t * 5;
        r[0] = sc; r[1] = bb.x; r[2] = bb.y; r[3] = bb.z; r[4] = bb.w;
    }
}

// ---------------- launch ----------------
extern "C" void kernel_launch(void* const* d_in, const int* in_sizes, int n_in,
                              void* d_out, int out_size) {
    const float* loc   = (const float*)d_in[0];   // [B,P,4]
    const float* conf  = (const float*)d_in[1];   // [B,P,2]
    const float* prior = (const float*)d_in[2];   // [P,4]

    int P = in_sizes[2] / 4;
    int B = in_sizes[1] / (2 * P);
    if (B > B_MAX) B = B_MAX;
    if (P > P_MAX) P = P_MAX;

    float* out = (float*)d_out;

    static const size_t SORT_SMEM = (size_t)CAP * sizeof(unsigned long long);   // 64 KB
    cudaFuncSetAttribute(sort_kernel, cudaFuncAttributeMaxDynamicSharedMemorySize, (int)SORT_SMEM);

    init_kernel<<<256, 256>>>(out, out_size, B);

    dim3 gscore((P + 511) / 512, B);
    score_kernel<<<gscore, 256>>>(conf, P);

    cutoff_kernel<<<B, 256>>>();

    dim3 gcomp((P + 1023) / 1024, B);
    compact_kernel<<<gcomp, 256>>>(P);

    sort_kernel<<<B, 1024, SORT_SMEM>>>(loc, prior, P);

    dim3 gmat((NMS_K + ITILE - 1) / ITILE, B);
    matrix_kernel<<<gmat, 256>>>();

    sweep_kernel<<<B, 256>>>(out);
}

// round 8
// speedup vs baseline: 3.0244x; 1.7367x over previous
#include <cuda_runtime.h>
#include <cstdint>

#define B_MAX   8
#define P_MAX   140000
#define NBINS   4096
#define CAP     8192       // compact buffer per batch (power of two, bitonic size)
#define NMS_K   5000       // candidates considered by NMS
#define NWORDS  157        // ceil(5000/32)
#define PAD     5120       // padded row length (i-dim) of transposed matrix
#define TOPK    750        // rows emitted per class
#define CONF_TH 0.05f
#define NMS_TH  0.3f
#define FULL    0xffffffffu
#define LOGIT05 -2.9444389791664403f   // logit(0.05)
#define PH1_W   64                      // phase-1 word range [0,64)
#define PH1_I   (PH1_W * 32)            // = 2048 candidates
#define ITILE   128

// ---------------- scratch (static device globals; no allocation) ----------------
__device__ float              g_t     [B_MAX * P_MAX];     // d = c1-c0 proxy (or -1e30 sentinel)
__device__ unsigned int       g_hist  [B_MAX * NBINS];
__device__ int                g_cnt   [B_MAX];
__device__ int                g_cutbin[B_MAX];
__device__ unsigned long long g_keys  [B_MAX * CAP];
__device__ float              g_cscore[B_MAX * NMS_K];
__device__ float4             g_cbox  [B_MAX * NMS_K];
__device__ float              g_carea [B_MAX * NMS_K];
__device__ unsigned int       g_matT  [(size_t)B_MAX * NWORDS * PAD];   // ~25.6 MB
// sweep state handoff
__device__ int                g_acc   [B_MAX * TOPK];
__device__ int                g_scnt  [B_MAX];
__device__ int                g_sdone [B_MAX];
__device__ int                g_need;

__device__ __forceinline__ int d_bin(float d) {
    int bin = (int)fmaf(d, 256.0f, 768.0f);        // monotone in d; keepers >= ~13
    return bin > NBINS - 1 ? NBINS - 1 : (bin < 0 ? 0 : bin);
}

// ---------------- init: zero output + scratch ----------------
__global__ void init_kernel(float* __restrict__ out, int out_size, int B) {
    int stride = gridDim.x * blockDim.x;
    int t = blockIdx.x * blockDim.x + threadIdx.x;
    for (int i = t; i < out_size; i += stride) out[i] = 0.0f;
    for (int i = t; i < B * NBINS; i += stride) g_hist[i] = 0u;
    for (int i = t; i < B; i += stride) g_cnt[i] = 0;
    for (int i = t; i < B * CAP; i += stride) g_keys[i] = ~0ull;
    if (t == 0) g_need = 0;
}

// ---------------- scores: d-proxy + threshold (exact band fallback) + histogram ----------------
__global__ void score_kernel(const float* __restrict__ conf, int P) {
    int b = blockIdx.y;
    int idx = (blockIdx.x * blockDim.x + threadIdx.x) * 2;
    if (idx >= P) return;
    size_t off = (size_t)b * P + idx;                    // even
    float4 c = reinterpret_cast<const float4*>(conf)[off >> 1];
    #pragma unroll
    for (int q = 0; q < 2; q++) {
        if (idx + q >= P) break;
        float c0 = q ? c.z : c.x;
        float c1 = q ? c.w : c.y;
        float d  = c1 - c0;                              // sigmoid(d) == softmax class-1
        bool keep;
        if (fabsf(d - LOGIT05) < 1e-3f) {                // boundary band: exact ref predicate
            float m  = fmaxf(c0, c1);
            float e0 = expf(c0 - m);
            float e1 = expf(c1 - m);
            keep = __fdiv_rn(e1, e0 + e1) > CONF_TH;
        } else keep = d > LOGIT05;
        g_t[off + q] = keep ? d : -1e30f;
        if (keep) atomicAdd(&g_hist[b * NBINS + d_bin(d)], 1u);
    }
}

// ---------------- cutoff: smallest bin t s.t. suffix count >= NMS_K ----------------
__global__ void cutoff_kernel() {
    int b = blockIdx.x;
    __shared__ unsigned int csum[256];
    int tid = threadIdx.x;
    unsigned int sum = 0;
    #pragma unroll
    for (int i = 0; i < NBINS / 256; i++) sum += g_hist[b * NBINS + tid * (NBINS / 256) + i];
    csum[tid] = sum;
    __syncthreads();
    if (tid == 0) {
        unsigned int acc = 0;
        int c = 255;
        for (; c >= 0; c--) {
            if (acc + csum[c] >= (unsigned)NMS_K) break;
            acc += csum[c];
        }
        int cut = 0;
        if (c >= 0) {
            int bin = c * (NBINS / 256) + (NBINS / 256) - 1;
            for (; bin >= c * (NBINS / 256); bin--) {
                acc += g_hist[b * NBINS + bin];
                if (acc >= (unsigned)NMS_K) break;
            }
            cut = (bin < c * (NBINS / 256)) ? c * (NBINS / 256) : bin;
        }
        g_cutbin[b] = cut;
    }
}

// ---------------- compact: keep bin>=cut-1, compute exact s, emit sortable keys ----------------
__global__ void compact_kernel(const float* __restrict__ conf, int P) {
    int b = blockIdx.y;
    int lane = threadIdx.x & 31;
    int base = (blockIdx.x * blockDim.x + threadIdx.x) * 4;
    int cut  = g_cutbin[b] - 1; if (cut < 0) cut = 0;    // one-bin margin (d vs s rounding)
    unsigned long long keys[4];
    int c = 0;
    if (base < P) {
        float4 t4 = *reinterpret_cast<const float4*>(&g_t[(size_t)b * P + base]);
        float tv[4] = {t4.x, t4.y, t4.z, t4.w};
        #pragma unroll
        for (int q = 0; q < 4; q++) {
            if (base + q < P) {
                float d = tv[q];
                if (d > -1e29f && d_bin(d) >= cut) {
                    // exact score, bit-identical to reference recipe
                    size_t ci = ((size_t)b * P + base + q) * 2;
                    float c0 = conf[ci], c1 = conf[ci + 1];
                    float m  = fmaxf(c0, c1);
                    float e0 = expf(c0 - m);
                    float e1 = expf(c1 - m);
                    float s  = __fdiv_rn(e1, e0 + e1);
                    unsigned kb = __float_as_uint(s);
                    keys[c++] = ((unsigned long long)(~kb) << 32) | (unsigned)(base + q);
                }
            }
        }
    }
    unsigned cnt = (unsigned)c;
    #pragma unroll
    for (int dd = 1; dd < 32; dd <<= 1) {
        unsigned n = __shfl_up_sync(FULL, cnt, dd);
        if (lane >= dd) cnt += n;
    }
    unsigned tot = __shfl_sync(FULL, cnt, 31);
    int basepos = 0;
    if (lane == 31 && tot) basepos = atomicAdd(&g_cnt[b], (int)tot);
    basepos = __shfl_sync(FULL, basepos, 31);
    int pos = basepos + (int)(cnt - (unsigned)c);
    for (int q = 0; q < c; q++, pos++)
        if (pos < CAP) g_keys[(size_t)b * CAP + pos] = keys[q];
}

// ---------------- bitonic span: phases k in [k_lo,k_hi] on chunk_elems-sized chunks ----------------
__global__ void bitonic_kernel(int chunk_elems, int k_lo, int k_hi, int do_decode,
                               const float* __restrict__ loc, const float* __restrict__ prior,
                               int P) {
    extern __shared__ unsigned long long sm[];
    int b = blockIdx.y, chunk = blockIdx.x, tid = threadIdx.x, T = blockDim.x;
    int gbase = chunk * chunk_elems;
    for (int i = tid; i < chunk_elems; i += T) sm[i] = g_keys[(size_t)b * CAP + gbase + i];
    __syncthreads();
    for (int k = k_lo; k <= k_hi; k <<= 1) {
        for (int j = k >> 1; j > 0; j >>= 1) {
            for (int i = tid; i < chunk_elems; i += T) {
                int ixj = i ^ j;
                if (ixj > i) {
                    unsigned long long a = sm[i], cc = sm[ixj];
                    bool up = (((gbase + i) & k) == 0);   // global direction bit
                    if ((a > cc) == up) { sm[i] = cc; sm[ixj] = a; }
                }
            }
            __syncthreads();
        }
    }
    for (int i = tid; i < chunk_elems; i += T) g_keys[(size_t)b * CAP + gbase + i] = sm[i];
    if (do_decode) {
        // only the final full-size pass decodes (chunk covers [0,CAP))
        for (int i = tid; i < NMS_K; i += T) {
            unsigned long long key = sm[i];
            unsigned int idx = (unsigned int)key;
            int o = b * NMS_K + i;
            if (idx < (unsigned int)P) {
                float  sc = __uint_as_float(~(unsigned)(key >> 32));
                float4 l  = reinterpret_cast<const float4*>(loc)[(size_t)b * P + idx];
                float4 pr = reinterpret_cast<const float4*>(prior)[idx];
                float cx = pr.x + l.x * 0.1f * pr.z;
                float cy = pr.y + l.y * 0.1f * pr.w;
                float w  = pr.z * expf(l.z * 0.2f);
                float h  = pr.w * expf(l.w * 0.2f);
                float x1 = cx - w * 0.5f;
                float y1 = cy - h * 0.5f;
                float x2 = x1 + w;
                float y2 = y1 + h;
                g_cscore[o] = sc;
                g_cbox[o]   = make_float4(x1, y1, x2, y2);
                g_carea[o]  = (x2 - x1) * (y2 - y1);
            } else {
                g_cscore[o] = -1.0f;
                g_cbox[o]   = make_float4(0.f, 0.f, 0.f, 0.f);
                g_carea[o]  = 0.0f;
            }
        }
    }
}

// ---------------- suppression bitmatrix (transposed), phased ----------------
// phase 0: tiles i0<PH1_I, words [i0>>5, PH1_W)      (what the phase-1 sweep consumes)
// phase 1: the remaining triangle; early-exits if all batches finished in phase 1
__global__ __launch_bounds__(256) void matrix_kernel(int phase) {
    if (phase && g_need == 0) return;
    __shared__ float4 sbi[ITILE];
    __shared__ float  sai[ITILE];
    int b  = blockIdx.y;
    int i0 = blockIdx.x * ITILE;
    int tid = threadIdx.x, lane = tid & 31, wid = tid >> 5;   // 8 warps

    for (int q = tid; q < ITILE; q += 256) {
        int i = i0 + q;
        if (i < NMS_K) { sbi[q] = g_cbox[b * NMS_K + i]; sai[q] = g_carea[b * NMS_K + i]; }
        else           { sbi[q] = make_float4(0,0,0,0);  sai[q] = 0.f; }
    }
    __syncthreads();

    int ilim = min(ITILE, NMS_K - i0);
    int wstart = i0 >> 5;
    int wend   = NWORDS;
    if (phase == 0) wend = PH1_W;
    else if (i0 < PH1_I) wstart = PH1_W;

    for (int w = wstart + wid; w < wend; w += 8) {
        int j = w * 32 + lane;
        bool jv = j < NMS_K;
        float4 bj = jv ? g_cbox[b * NMS_K + j] : make_float4(0,0,0,0);
        float  aj = jv ? g_carea[b * NMS_K + j] : 0.f;
        size_t base = ((size_t)(b * NWORDS + w)) * PAD + i0;
        unsigned myw = 0;
        for (int ii = 0; ii < ilim; ii++) {
            int i = i0 + ii;
            float4 bi = sbi[ii];                      // broadcast (conflict-free)
            float  ai = sai[ii];
            float xx1 = fmaxf(bj.x, bi.x), yy1 = fmaxf(bj.y, bi.y);
            float xx2 = fminf(bj.z, bi.z), yy2 = fminf(bj.w, bi.w);
            float inter = fmaxf(xx2 - xx1, 0.f) * fmaxf(yy2 - yy1, 0.f);
            float uni   = aj - inter + ai;
            // division-free IoU sign test; exact __fdiv_rn only in the boundary band
            float d = fmaf(-NMS_TH, uni, inter);
            bool flag;
            if (fabsf(d) <= 1e-6f * fabsf(uni))
                flag = __fdiv_rn(inter, uni) > NMS_TH;
            else
                flag = d > 0.f;
            flag = flag && jv && (j > i);
            unsigned bal = __ballot_sync(FULL, flag);
            if ((ii & 31) == lane) myw = bal;
            if ((ii & 31) == 31) g_matT[base + (ii - 31) + lane] = myw;   // coalesced
        }
        if (ilim & 31) g_matT[base + (ilim & ~31) + lane] = myw;
    }
}

// ---------------- sweep phase 1: words [0, PH1_W); saves state ----------------
__global__ void sweep1_kernel() {
    __shared__ unsigned validw[PH1_W];
    __shared__ int      s_acc[TOPK];
    __shared__ int      s_cnt;

    int b = blockIdx.x, tid = threadIdx.x, lane = tid & 31, wid = tid >> 5;

    for (int w = wid; w < PH1_W; w += 8) {
        int i = w * 32 + lane;
        unsigned m = __ballot_sync(FULL, (i < NMS_K) && (g_cscore[b * NMS_K + i] > 0.0f));
        if (lane == 0) validw[w] = m;
    }
    __syncthreads();

    if (wid == 0) {
        int cnt = 0;
        for (int w = 0; w < PH1_W && cnt < TOPK; w++) {
            size_t base = ((size_t)(b * NWORDS + w)) * PAD;
            unsigned rem = 0;
            for (int q = lane; q < cnt; q += 32)
                rem |= g_matT[base + s_acc[q]];
            rem = __reduce_or_sync(FULL, rem);
            unsigned pre = g_matT[base + w * 32 + lane];
            unsigned avail = validw[w] & ~rem;
            while (avail && cnt < TOPK) {
                int bit = __ffs(avail) - 1;
                int i = w * 32 + bit;
                if (lane == 0) s_acc[cnt] = i;
                cnt++;
                avail &= ~(1u << bit);
                avail &= ~__shfl_sync(FULL, pre, bit);
            }
            __syncwarp();
        }
        if (lane == 0) {
            s_cnt = cnt;
            g_scnt[b] = cnt;
            int done = (cnt >= TOPK);
            g_sdone[b] = done;
            if (!done) atomicOr(&g_need, 1);
        }
    }
    __syncthreads();
    int cnt = s_cnt;
    for (int t = tid; t < cnt; t += blockDim.x) g_acc[b * TOPK + t] = s_acc[t];
}

// ---------------- sweep phase 2: resume (if needed) + emit output ----------------
__global__ void sweep2_kernel(float* __restrict__ out) {
    __shared__ unsigned validw[NWORDS];
    __shared__ int      s_acc[TOPK];
    __shared__ int      s_cnt;

    int b = blockIdx.x, tid = threadIdx.x, lane = tid & 31, wid = tid >> 5;
    int done = g_sdone[b];
    int cnt0 = g_scnt[b];

    for (int t = tid; t < cnt0; t += blockDim.x) s_acc[t] = g_acc[b * TOPK + t];
    if (tid == 0) s_cnt = cnt0;

    if (!done) {
        for (int w = PH1_W + wid; w < NWORDS; w += 8) {
            int i = w * 32 + lane;
            unsigned m = __ballot_sync(FULL, (i < NMS_K) && (g_cscore[b * NMS_K + i] > 0.0f));
            if (lane == 0) validw[w] = m;
        }
    }
    __syncthreads();

    if (!done && wid == 0) {
        int cnt = cnt0;
        for (int w = PH1_W; w < NWORDS && cnt < TOPK; w++) {
            size_t base = ((size_t)(b * NWORDS + w)) * PAD;
            unsigned rem = 0;
            for (int q = lane; q < cnt; q += 32)
                rem |= g_matT[base + s_acc[q]];
            rem = __reduce_or_sync(FULL, rem);
            unsigned pre = g_matT[base + w * 32 + lane];
            unsigned avail = validw[w] & ~rem;
            while (avail && cnt < TOPK) {
                int bit = __ffs(avail) - 1;
                int i = w * 32 + bit;
                if (lane == 0) s_acc[cnt] = i;
                cnt++;
                avail &= ~(1u << bit);
                avail &= ~__shfl_sync(FULL, pre, bit);
            }
            __syncwarp();
        }
        if (lane == 0) s_cnt = cnt;
    }
    __syncthreads();

    int cnt = s_cnt;
    float* orow = out + ((size_t)b * 2 + 1) * TOPK * 5;   // class 1
    for (int t = tid; t < cnt; t += blockDim.x) {
        int i = s_acc[t];
        float4 bb = g_cbox[b * NMS_K + i];
        float  sc = g_cscore[b * NMS_K + i];
        float* r = orow + t * 5;
        r[0] = sc; r[1] = bb.x; r[2] = bb.y; r[3] = bb.z; r[4] = bb.w;
    }
}

// ---------------- launch ----------------
extern "C" void kernel_launch(void* const* d_in, const int* in_sizes, int n_in,
                              void* d_out, int out_size) {
    const float* loc   = (const float*)d_in[0];   // [B,P,4]
    const float* conf  = (const float*)d_in[1];   // [B,P,2]
    const float* prior = (const float*)d_in[2];   // [P,4]

    int P = in_sizes[2] / 4;
    int B = in_sizes[1] / (2 * P);
    if (B > B_MAX) B = B_MAX;
    if (P > P_MAX) P = P_MAX;

    float* out = (float*)d_out;

    static const size_t SORT_SMEM = (size_t)CAP * sizeof(unsigned long long);   // 64 KB max
    cudaFuncSetAttribute(bitonic_kernel, cudaFuncAttributeMaxDynamicSharedMemorySize, (int)SORT_SMEM);

    init_kernel<<<256, 256>>>(out, out_size, B);

    dim3 gscore((P + 511) / 512, B);
    score_kernel<<<gscore, 256>>>(conf, P);

    cutoff_kernel<<<B, 256>>>();

    dim3 gcomp((P + 1023) / 1024, B);
    compact_kernel<<<gcomp, 256>>>(conf, P);

    // split bitonic: k<=2048 in 2048-chunks, k=4096 in 4096-chunks, k=8192 full (+decode)
    bitonic_kernel<<<dim3(4, B), 1024, 2048 * 8>>>(2048, 2,    2048, 0, loc, prior, P);
    bitonic_kernel<<<dim3(2, B), 1024, 4096 * 8>>>(4096, 4096, 4096, 0, loc, prior, P);
    bitonic_kernel<<<dim3(1, B), 1024, 8192 * 8>>>(8192, 8192, 8192, 1, loc, prior, P);

    // phase 1: top-2048 triangle, sweep words [0,64)
    matrix_kernel<<<dim3(PH1_I / ITILE, B), 256>>>(0);
    sweep1_kernel<<<B, 256>>>();

    // phase 2: remainder (early-exits when all batches finished) + resume/emit
    matrix_kernel<<<dim3((NMS_K + ITILE - 1) / ITILE, B), 256>>>(1);
    sweep2_kernel<<<B, 256>>>(out);
}